// round 15
// baseline (speedup 1.0000x reference)
#include <cuda_runtime.h>
#include <cuda_bf16.h>
#include <cstdint>
#include <cstddef>

// Problem constants
#define BB   2
#define SS   2048
#define DD   512
#define HH   8
#define DEP  64
#define BSD  (BB*SS*DD)

// ---------------- scratch (device globals; no allocation allowed) ----------------
__device__ float g_q[BB*HH*SS*DEP];   // [B,H,S,64] projected Q
__device__ float g_k[BB*HH*SS*DEP];   // [B,H,S,64] projected K
__device__ float g_v[BB*HH*SS*DEP];   // [B,H,S,64] projected V
__device__ float g_c[BB*SS*DD];       // [B,S,D] concat(attention)
__device__ float g_cm[(size_t)BB*HH*SS*32];   // per-(row,chunk) max (4 MB)

// =================================================================================
// Projection GEMMs (R12/R13 measured version, unchanged)
// =================================================================================
__device__ __forceinline__ void gemm_body(const float* __restrict__ X,
                                          const float* __restrict__ W,
                                          const float* __restrict__ bias,
                                          float* __restrict__ out, int mode)
{
    __shared__ float Xs[2][16*132];
    __shared__ float Wt[2][16*132];
    const int t  = threadIdx.x;
    const int tx = t & 15, ty = t >> 4;
    const int m0 = blockIdx.x * 128, n0 = blockIdx.y * 128;

    float acc[8][8];
    #pragma unroll
    for (int i = 0; i < 8; i++)
        #pragma unroll
        for (int j = 0; j < 8; j++) acc[i][j] = 0.f;

    #pragma unroll
    for (int i = 0; i < 8; i++) {
        int idx = t + i*256;
        int k = idx & 15, m = idx >> 4;
        Xs[0][k*132 + m] = X[(size_t)(m0 + m)*DD + k];
    }
    #pragma unroll
    for (int i = 0; i < 8; i++) {
        int idx = t + i*256;
        int n = idx & 127, k = idx >> 7;
        Wt[0][k*132 + n] = W[(size_t)k*DD + n0 + n];
    }
    __syncthreads();

    const int NSTG = DD / 16;
    for (int s = 0; s < NSTG; s++) {
        const int cur = s & 1;
        if (s + 1 < NSTG) {
            const int nxt = cur ^ 1;
            const int kb = (s + 1) * 16;
            #pragma unroll
            for (int i = 0; i < 8; i++) {
                int idx = t + i*256;
                int k = idx & 15, m = idx >> 4;
                Xs[nxt][k*132 + m] = X[(size_t)(m0 + m)*DD + kb + k];
            }
            #pragma unroll
            for (int i = 0; i < 8; i++) {
                int idx = t + i*256;
                int n = idx & 127, k = idx >> 7;
                Wt[nxt][k*132 + n] = W[(size_t)(kb + k)*DD + n0 + n];
            }
        }
        #pragma unroll
        for (int k = 0; k < 16; k++) {
            float4 a0 = *(const float4*)&Xs[cur][k*132 + ty*8];
            float4 a1 = *(const float4*)&Xs[cur][k*132 + ty*8 + 4];
            float4 b0 = *(const float4*)&Wt[cur][k*132 + tx*8];
            float4 b1 = *(const float4*)&Wt[cur][k*132 + tx*8 + 4];
            float a[8] = {a0.x,a0.y,a0.z,a0.w,a1.x,a1.y,a1.z,a1.w};
            float b[8] = {b0.x,b0.y,b0.z,b0.w,b1.x,b1.y,b1.z,b1.w};
            #pragma unroll
            for (int i = 0; i < 8; i++)
                #pragma unroll
                for (int j = 0; j < 8; j++) acc[i][j] += a[i]*b[j];
        }
        __syncthreads();
    }

    #pragma unroll
    for (int i = 0; i < 8; i++) {
        int m = m0 + ty*8 + i;
        int b_ = m >> 11, s2 = m & (SS - 1);
        #pragma unroll
        for (int j = 0; j < 8; j++) {
            int n = n0 + tx*8 + j;
            float v = acc[i][j] + bias[n];
            if (mode == 0) {
                int h = n >> 6, d = n & 63;
                out[(((size_t)(b_*HH + h)*SS + s2) << 6) + d] = v;
            } else {
                out[(size_t)m*DD + n] = v;
            }
        }
    }
}

__global__ __launch_bounds__(256, 2) void gemm_qkv(
    const float* __restrict__ q_in, const float* __restrict__ k_in,
    const float* __restrict__ v_in,
    const float* __restrict__ Wq, const float* __restrict__ bq,
    const float* __restrict__ Wk, const float* __restrict__ bk,
    const float* __restrict__ Wv, const float* __restrict__ bv,
    float* __restrict__ gq, float* __restrict__ gk, float* __restrict__ gv)
{
    const float *X, *W, *bias; float* out;
    if (blockIdx.z == 0)      { X = q_in; W = Wq; bias = bq; out = gq; }
    else if (blockIdx.z == 1) { X = k_in; W = Wk; bias = bk; out = gk; }
    else                      { X = v_in; W = Wv; bias = bv; out = gv; }
    gemm_body(X, W, bias, out, 0);
}

__global__ __launch_bounds__(256, 2) void gemm_out(
    const float* __restrict__ X, const float* __restrict__ W,
    const float* __restrict__ bias, float* __restrict__ out)
{
    gemm_body(X, W, bias, out, 1);
}

// =================================================================================
// bf16 split helpers + mma.sync machinery
// =================================================================================
__device__ __forceinline__ uint32_t sptr(const void* p) {
    return (uint32_t)__cvta_generic_to_shared(p);
}
__device__ __forceinline__ void split4(float4 v, uint2& hi, uint2& lo) {
    __nv_bfloat16 h0=__float2bfloat16(v.x), h1=__float2bfloat16(v.y),
                  h2=__float2bfloat16(v.z), h3=__float2bfloat16(v.w);
    __nv_bfloat16 l0=__float2bfloat16(v.x-__bfloat162float(h0)),
                  l1=__float2bfloat16(v.y-__bfloat162float(h1)),
                  l2=__float2bfloat16(v.z-__bfloat162float(h2)),
                  l3=__float2bfloat16(v.w-__bfloat162float(h3));
    __nv_bfloat162 ph0=__halves2bfloat162(h0,h1), ph1=__halves2bfloat162(h2,h3);
    __nv_bfloat162 pl0=__halves2bfloat162(l0,l1), pl1=__halves2bfloat162(l2,l3);
    hi = make_uint2(*(uint32_t*)&ph0, *(uint32_t*)&ph1);
    lo = make_uint2(*(uint32_t*)&pl0, *(uint32_t*)&pl1);
}
__device__ __forceinline__ void bsplit(float x, __nv_bfloat16& h, __nv_bfloat16& l) {
    h = __float2bfloat16(x);
    l = __float2bfloat16(x - __bfloat162float(h));
}

// pitch 72 bf16 = 144 bytes per row (conflict-free for ldmatrix: 16B bank shift/row)
#define PH 72
#define LDSM_X4(r, base_chr, Rb, kelem) do {                                        \
    uint32_t _a = sptr((base_chr) + ((Rb) + (lane & 15))*144 + (kelem)*2            \
                       + ((lane >> 4) & 1)*16);                                     \
    asm volatile("ldmatrix.sync.aligned.m8n8.x4.shared.b16 {%0,%1,%2,%3}, [%4];"    \
        : "=r"((r)[0]),"=r"((r)[1]),"=r"((r)[2]),"=r"((r)[3]) : "r"(_a)); } while(0)
#define LDSM_X2(r, base_chr, Nb, kelem) do {                                        \
    uint32_t _a = sptr((base_chr) + ((Nb) + (lane & 7))*144 + (kelem)*2             \
                       + ((lane >> 3) & 1)*16);                                     \
    asm volatile("ldmatrix.sync.aligned.m8n8.x2.shared.b16 {%0,%1}, [%2];"          \
        : "=r"((r)[0]),"=r"((r)[1]) : "r"(_a)); } while(0)
#define MMA_BF16(c, a, bb)                                                          \
    asm volatile("mma.sync.aligned.m16n8k16.row.col.f32.bf16.bf16.f32 "             \
        "{%0,%1,%2,%3}, {%4,%5,%6,%7}, {%8,%9}, {%0,%1,%2,%3};"                     \
        : "+f"((c)[0]),"+f"((c)[1]),"+f"((c)[2]),"+f"((c)[3])                       \
        : "r"((a)[0]),"r"((a)[1]),"r"((a)[2]),"r"((a)[3]), "r"((bb)[0]),"r"((bb)[1]))

// smem byte offsets
#define B_QH 0
#define B_QL 9216
#define B_BH 18432
#define B_BL 36864
#define B_DK 55296      // float [64][68]
#define B_DE 72704      // float [64][132] ring (128 slots)
#define B_RM 106496
#define B_RS 106752
#define SM3_BYTES 107008
// phase-2 overlays (inside B region)
#define B_VH 18432
#define B_VL 27648
#define B_P2H 36864
#define B_P2L 46080

// =================================================================================
// Tensor-core fused attention (R13 structure) with halved-expf softmax:
// phase 1 stores e = exp(l - chunk_max) and saves chunk_max to g_cm;
// phase 2 rescales with ONE expf per (thread, chunk) instead of per element.
// =================================================================================
__global__ __launch_bounds__(256, 2) void attn3(const float* __restrict__ E,
                                                float* __restrict__ attn)
{
    extern __shared__ char smc[];
    float* DK = (float*)(smc + B_DK);
    float* DE = (float*)(smc + B_DE);
    float* rm = (float*)(smc + B_RM);
    float* rs = (float*)(smc + B_RS);

    const int t    = threadIdx.x;
    const int lane = t & 31, wp = t >> 5;
    const int mi = wp & 3, nh = wp >> 2;
    const int qt = 31 - (int)blockIdx.x;   // big tiles first
    const int q0 = qt * 64;
    const int h  = blockIdx.y, b = blockIdx.z;
    const int bh = b*HH + h;
    const float* qb = g_q + (size_t)bh*SS*DEP;
    const float* kb = g_k + (size_t)bh*SS*DEP;
    const float* vb = g_v + (size_t)bh*SS*DEP;
    float* arow_base = attn + ((size_t)bh*SS + q0) * SS;
    const int ql = t >> 2, ks4 = t & 3;
    const int nch = qt + 1;
    float* cmrow = g_cm + ((size_t)bh*SS + q0 + ql)*32;

    // ---- load Q (split) + prologue E rows into B[0,64) (split) ----
    #pragma unroll
    for (int it = 0; it < 4; it++) {
        int idx = t + it*256;
        int r = idx >> 4, d4 = (idx & 15) << 2;
        float4 v = *(const float4*)(qb + (size_t)(q0 + r)*DEP + d4);
        uint2 hi, lo; split4(v, hi, lo);
        *(uint2*)(smc + B_QH + r*144 + d4*2) = hi;
        *(uint2*)(smc + B_QL + r*144 + d4*2) = lo;
    }
    {
        const int er0 = SS - 64 - q0;
        #pragma unroll
        for (int it = 0; it < 4; it++) {
            int idx = t + it*256;
            int r = idx >> 4, d4 = (idx & 15) << 2;
            float4 v = *(const float4*)(E + (size_t)(er0 + r)*DEP + d4);
            uint2 hi, lo; split4(v, hi, lo);
            *(uint2*)(smc + B_BH + r*144 + d4*2) = hi;
            *(uint2*)(smc + B_BL + r*144 + d4*2) = lo;
        }
    }
    if (t < 64) { rm[t] = -1e30f; rs[t] = 0.f; }
    __syncthreads();

    // ---- prologue MMA: Q @ E_pro^T -> DE slots [0,64) ----
    {
        float c[4][4];
        #pragma unroll
        for (int j = 0; j < 4; j++)
            #pragma unroll
            for (int e = 0; e < 4; e++) c[j][e] = 0.f;
        uint32_t Ah[4], Al[4], Bh[2], Bl[2];
        #pragma unroll
        for (int ks = 0; ks < 4; ks++) {
            LDSM_X4(Ah, smc + B_QH, mi*16, ks*16);
            LDSM_X4(Al, smc + B_QL, mi*16, ks*16);
            #pragma unroll
            for (int j = 0; j < 4; j++) {
                int n0 = (nh*4 + j)*8;
                LDSM_X2(Bh, smc + B_BH, n0, ks*16);
                LDSM_X2(Bl, smc + B_BL, n0, ks*16);
                MMA_BF16(c[j], Ah, Bh);
                MMA_BF16(c[j], Ah, Bl);
                MMA_BF16(c[j], Al, Bh);
            }
        }
        int r = mi*16 + (lane >> 2), cc = 2*(lane & 3);
        #pragma unroll
        for (int j = 0; j < 4; j++) {
            int col = (nh*4 + j)*8 + cc;
            *(float2*)(DE + r*132 + col)       = make_float2(c[j][0], c[j][1]);
            *(float2*)(DE + (r + 8)*132 + col) = make_float2(c[j][2], c[j][3]);
        }
    }
    __syncthreads();

    // ---------------- phase 1 main loop ----------------
    for (int kt = 0; kt < nch; kt++) {
        const int k0 = kt*64;
        #pragma unroll
        for (int it = 0; it < 4; it++) {
            int idx = t + it*256;
            int r = idx >> 4, d4 = (idx & 15) << 2;
            float4 v = *(const float4*)(kb + (size_t)(k0 + r)*DEP + d4);
            uint2 hi, lo; split4(v, hi, lo);
            *(uint2*)(smc + B_BH + r*144 + d4*2) = hi;
            *(uint2*)(smc + B_BL + r*144 + d4*2) = lo;
        }
        {
            const int ern = SS - q0 + 64*kt;
            #pragma unroll
            for (int it = 0; it < 4; it++) {
                int idx = t + it*256;
                int r = idx >> 4, d4 = (idx & 15) << 2;
                int er = ern + r;
                float4 v = (er < SS) ? *(const float4*)(E + (size_t)er*DEP + d4)
                                     : make_float4(0.f, 0.f, 0.f, 0.f);
                uint2 hi, lo; split4(v, hi, lo);
                *(uint2*)(smc + B_BH + (64 + r)*144 + d4*2) = hi;
                *(uint2*)(smc + B_BL + (64 + r)*144 + d4*2) = lo;
            }
        }
        __syncthreads();

        // D(64x128) = Q @ B^T
        float c[8][4];
        #pragma unroll
        for (int j = 0; j < 8; j++)
            #pragma unroll
            for (int e = 0; e < 4; e++) c[j][e] = 0.f;
        {
            uint32_t Ah[4], Al[4], Bh[2], Bl[2];
            #pragma unroll
            for (int ks = 0; ks < 4; ks++) {
                LDSM_X4(Ah, smc + B_QH, mi*16, ks*16);
                LDSM_X4(Al, smc + B_QL, mi*16, ks*16);
                #pragma unroll
                for (int j = 0; j < 8; j++) {
                    int n0 = (nh*8 + j)*8;
                    LDSM_X2(Bh, smc + B_BH, n0, ks*16);
                    LDSM_X2(Bl, smc + B_BL, n0, ks*16);
                    MMA_BF16(c[j], Ah, Bh);
                    MMA_BF16(c[j], Ah, Bl);
                    MMA_BF16(c[j], Al, Bh);
                }
            }
        }
        {
            int r = mi*16 + (lane >> 2), cc = 2*(lane & 3);
            if (nh == 0) {
                #pragma unroll
                for (int j = 0; j < 8; j++) {
                    int col = j*8 + cc;
                    *(float2*)(DK + r*68 + col)       = make_float2(c[j][0], c[j][1]);
                    *(float2*)(DK + (r + 8)*68 + col) = make_float2(c[j][2], c[j][3]);
                }
            } else {
                int sb = (64*(kt + 1)) & 127;
                #pragma unroll
                for (int j = 0; j < 8; j++) {
                    int slot = sb + j*8 + cc;
                    *(float2*)(DE + r*132 + slot)       = make_float2(c[j][0], c[j][1]);
                    *(float2*)(DE + (r + 8)*132 + slot) = make_float2(c[j][2], c[j][3]);
                }
            }
        }
        __syncthreads();

        // gather + mask; chunk-max reduce FIRST; store e = exp(l - cm); stats
        {
            const float* dkr = DK + ql*68;
            const float* der = DE + ql*132;
            const int slotbase = 64*kt + 63 - ql;
            float l[16];
            float lmax = -1e30f;
            #pragma unroll
            for (int j = 0; j < 16; j++) {
                int kl = ks4 + 4*j;
                float v = dkr[kl] + der[(slotbase + kl) & 127];
                v = (k0 + kl <= q0 + ql) ? v*0.125f : -1e30f;
                l[j] = v;
                lmax = fmaxf(lmax, v);
            }
            // chunk-row max across the 4-thread group
            lmax = fmaxf(lmax, __shfl_xor_sync(0xffffffffu, lmax, 1));
            lmax = fmaxf(lmax, __shfl_xor_sync(0xffffffffu, lmax, 2));

            float lsum = 0.f;
            float* ar = arow_base + (size_t)ql*SS + k0;
            #pragma unroll
            for (int j = 0; j < 16; j++) {
                float e = __expf(l[j] - lmax);   // masked -> exact 0
                lsum += e;
                ar[ks4 + 4*j] = e;
            }
            lsum += __shfl_xor_sync(0xffffffffu, lsum, 1);
            lsum += __shfl_xor_sync(0xffffffffu, lsum, 2);

            if (ks4 == 0) {
                cmrow[kt] = lmax;
                float mo = rm[ql];
                float nm = fmaxf(mo, lmax);
                rs[ql] = rs[ql]*__expf(mo - nm) + lsum*__expf(lmax - nm);
                rm[ql] = nm;
            }
        }
        __syncthreads();
    }

    const float rmax = rm[ql];
    const float rinv = 1.f / rs[ql];

    // ---------------- phase 2: rescale + O = P @ V (mma) ----------------
    __nv_bfloat16* Vh  = (__nv_bfloat16*)(smc + B_VH);
    __nv_bfloat16* Vl  = (__nv_bfloat16*)(smc + B_VL);
    __nv_bfloat16* P2h = (__nv_bfloat16*)(smc + B_P2H);
    __nv_bfloat16* P2l = (__nv_bfloat16*)(smc + B_P2L);
    float o[4][4];
    #pragma unroll
    for (int j = 0; j < 4; j++)
        #pragma unroll
        for (int e = 0; e < 4; e++) o[j][e] = 0.f;

    for (int kt = 0; kt < nch; kt++) {
        const int k0 = kt*64;
        __syncthreads();
        #pragma unroll
        for (int it = 0; it < 4; it++) {
            int idx = t + it*256;
            int k = idx >> 4, d4 = (idx & 15) << 2;
            float4 v = *(const float4*)(vb + (size_t)(k0 + k)*DEP + d4);
            float vv[4] = {v.x, v.y, v.z, v.w};
            #pragma unroll
            for (int e = 0; e < 4; e++) {
                __nv_bfloat16 hb, lb; bsplit(vv[e], hb, lb);
                Vh[(d4 + e)*PH + k] = hb;
                Vl[(d4 + e)*PH + k] = lb;
            }
        }
        // rescale: ONE expf per (thread, chunk)
        const float scale = __expf(cmrow[kt] - rmax) * rinv;
        float* ar = arow_base + (size_t)ql*SS + k0;
        #pragma unroll
        for (int j = 0; j < 16; j++) {
            int kl = ks4 + 4*j;
            float wgt = ar[kl] * scale;          // masked -> exact 0
            ar[kl] = wgt;
            __nv_bfloat16 hb, lb; bsplit(wgt, hb, lb);
            P2h[ql*PH + kl] = hb;
            P2l[ql*PH + kl] = lb;
        }
        __syncthreads();
        {
            uint32_t Ah[4], Al[4], Bh[2], Bl[2];
            #pragma unroll
            for (int ks = 0; ks < 4; ks++) {
                LDSM_X4(Ah, smc + B_P2H, mi*16, ks*16);
                LDSM_X4(Al, smc + B_P2L, mi*16, ks*16);
                #pragma unroll
                for (int j = 0; j < 4; j++) {
                    int n0 = (nh*4 + j)*8;
                    LDSM_X2(Bh, smc + B_VH, n0, ks*16);
                    LDSM_X2(Bl, smc + B_VL, n0, ks*16);
                    MMA_BF16(o[j], Ah, Bh);
                    MMA_BF16(o[j], Ah, Bl);
                    MMA_BF16(o[j], Al, Bh);
                }
            }
        }
    }

    // zero-fill strictly-upper tail columns [nch*64, S)
    const int kstart = nch*64;
    if (kstart < SS) {
        const int len4 = (SS - kstart) >> 2;
        const int tot = 64 * len4;
        for (int idx = t; idx < tot; idx += 256) {
            int row = idx / len4, ccc = idx - row*len4;
            ((float4*)(arow_base + (size_t)row*SS + kstart))[ccc] =
                make_float4(0.f, 0.f, 0.f, 0.f);
        }
    }

    // O -> concat buffer [B,S,D]
    {
        int r = mi*16 + (lane >> 2), cc = 2*(lane & 3);
        #pragma unroll
        for (int j = 0; j < 4; j++) {
            int d = (nh*4 + j)*8 + cc;
            *(float2*)(g_c + ((size_t)b*SS + q0 + r)*DD + h*64 + d) =
                make_float2(o[j][0], o[j][1]);
            *(float2*)(g_c + ((size_t)b*SS + q0 + r + 8)*DD + h*64 + d) =
                make_float2(o[j][2], o[j][3]);
        }
    }
}

// =================================================================================
// launch
// inputs: 0 v_in, 1 k_in, 2 q_in, 3 mask(unused), 4 Wq, 5 bq, 6 Wk, 7 bk,
//         8 Wv, 9 bv, 10 Wo, 11 bo, 12 E
// output: [output (B*S*D floats)] ++ [attention_weights (B*H*S*S floats)]
// =================================================================================
extern "C" void kernel_launch(void* const* d_in, const int* in_sizes, int n_in,
                              void* d_out, int out_size)
{
    (void)in_sizes; (void)n_in; (void)out_size;
    const float* v_in = (const float*)d_in[0];
    const float* k_in = (const float*)d_in[1];
    const float* q_in = (const float*)d_in[2];
    const float* Wq   = (const float*)d_in[4];
    const float* bq   = (const float*)d_in[5];
    const float* Wk   = (const float*)d_in[6];
    const float* bk   = (const float*)d_in[7];
    const float* Wv   = (const float*)d_in[8];
    const float* bv   = (const float*)d_in[9];
    const float* Wo   = (const float*)d_in[10];
    const float* bo   = (const float*)d_in[11];
    const float* E    = (const float*)d_in[12];

    float* out  = (float*)d_out;
    float* attn = out + (size_t)BSD;

    float *gq, *gk, *gv, *gc;
    cudaGetSymbolAddress((void**)&gq, g_q);
    cudaGetSymbolAddress((void**)&gk, g_k);
    cudaGetSymbolAddress((void**)&gv, g_v);
    cudaGetSymbolAddress((void**)&gc, g_c);

    cudaFuncSetAttribute(attn3,
                         cudaFuncAttributeMaxDynamicSharedMemorySize, SM3_BYTES);

    gemm_qkv<<<dim3(32, 4, 3), 256>>>(q_in, k_in, v_in,
                                      Wq, bq, Wk, bk, Wv, bv,
                                      gq, gk, gv);
    attn3<<<dim3(32, HH, BB), 256, SM3_BYTES>>>(E, attn);
    gemm_out<<<dim3(32, 4), 256>>>(gc, Wo, bo, out);
}

// round 17
// speedup vs baseline: 1.2773x; 1.2773x over previous
#include <cuda_runtime.h>
#include <cuda_bf16.h>
#include <cstdint>
#include <cstddef>

// Problem constants
#define BB   2
#define SS   2048
#define DD   512
#define HH   8
#define DEP  64
#define BSD  (BB*SS*DD)

// ---------------- scratch (device globals; no allocation allowed) ----------------
__device__ float g_q[BB*HH*SS*DEP];   // [B,H,S,64] projected Q
__device__ float g_k[BB*HH*SS*DEP];   // [B,H,S,64] projected K
__device__ float g_v[BB*HH*SS*DEP];   // [B,H,S,64] projected V
__device__ float g_c[BB*SS*DD];       // [B,S,D] concat(attention)
__device__ __nv_bfloat16 g_wh[4][DD*DD];   // W^T hi, [n][k]
__device__ __nv_bfloat16 g_wl[4][DD*DD];   // W^T lo, [n][k]

// =================================================================================
// helpers
// =================================================================================
__device__ __forceinline__ uint32_t sptr(const void* p) {
    return (uint32_t)__cvta_generic_to_shared(p);
}
__device__ __forceinline__ void split4(float4 v, uint2& hi, uint2& lo) {
    __nv_bfloat16 h0=__float2bfloat16(v.x), h1=__float2bfloat16(v.y),
                  h2=__float2bfloat16(v.z), h3=__float2bfloat16(v.w);
    __nv_bfloat16 l0=__float2bfloat16(v.x-__bfloat162float(h0)),
                  l1=__float2bfloat16(v.y-__bfloat162float(h1)),
                  l2=__float2bfloat16(v.z-__bfloat162float(h2)),
                  l3=__float2bfloat16(v.w-__bfloat162float(h3));
    __nv_bfloat162 ph0=__halves2bfloat162(h0,h1), ph1=__halves2bfloat162(h2,h3);
    __nv_bfloat162 pl0=__halves2bfloat162(l0,l1), pl1=__halves2bfloat162(l2,l3);
    hi = make_uint2(*(uint32_t*)&ph0, *(uint32_t*)&ph1);
    lo = make_uint2(*(uint32_t*)&pl0, *(uint32_t*)&pl1);
}
__device__ __forceinline__ void bsplit(float x, __nv_bfloat16& h, __nv_bfloat16& l) {
    h = __float2bfloat16(x);
    l = __float2bfloat16(x - __bfloat162float(h));
}

#define MMA_BF16(c, a, bb)                                                          \
    asm volatile("mma.sync.aligned.m16n8k16.row.col.f32.bf16.bf16.f32 "             \
        "{%0,%1,%2,%3}, {%4,%5,%6,%7}, {%8,%9}, {%0,%1,%2,%3};"                     \
        : "+f"((c)[0]),"+f"((c)[1]),"+f"((c)[2]),"+f"((c)[3])                       \
        : "r"((a)[0]),"r"((a)[1]),"r"((a)[2]),"r"((a)[3]), "r"((bb)[0]),"r"((bb)[1]))

// pitch-144 variants (attn kernel)
#define LDSM_X4(r, base_chr, Rb, kelem) do {                                        \
    uint32_t _a = sptr((base_chr) + ((Rb) + (lane & 15))*144 + (kelem)*2            \
                       + ((lane >> 4) & 1)*16);                                     \
    asm volatile("ldmatrix.sync.aligned.m8n8.x4.shared.b16 {%0,%1,%2,%3}, [%4];"    \
        : "=r"((r)[0]),"=r"((r)[1]),"=r"((r)[2]),"=r"((r)[3]) : "r"(_a)); } while(0)
#define LDSM_X2(r, base_chr, Nb, kelem) do {                                        \
    uint32_t _a = sptr((base_chr) + ((Nb) + (lane & 7))*144 + (kelem)*2             \
                       + ((lane >> 3) & 1)*16);                                     \
    asm volatile("ldmatrix.sync.aligned.m8n8.x2.shared.b16 {%0,%1}, [%2];"          \
        : "=r"((r)[0]),"=r"((r)[1]) : "r"(_a)); } while(0)
// pitch-80 variants (projection kernels)
#define LDSM_X4P(r, base_chr, Rb, kelem) do {                                       \
    uint32_t _a = sptr((char*)(base_chr) + ((Rb) + (lane & 15))*80 + (kelem)*2      \
                       + ((lane >> 4) & 1)*16);                                     \
    asm volatile("ldmatrix.sync.aligned.m8n8.x4.shared.b16 {%0,%1,%2,%3}, [%4];"    \
        : "=r"((r)[0]),"=r"((r)[1]),"=r"((r)[2]),"=r"((r)[3]) : "r"(_a)); } while(0)
#define LDSM_X2P(r, base_chr, Nb, kelem) do {                                       \
    uint32_t _a = sptr((char*)(base_chr) + ((Nb) + (lane & 7))*80 + (kelem)*2       \
                       + ((lane >> 3) & 1)*16);                                     \
    asm volatile("ldmatrix.sync.aligned.m8n8.x2.shared.b16 {%0,%1}, [%2];"          \
        : "=r"((r)[0]),"=r"((r)[1]) : "r"(_a)); } while(0)

// =================================================================================
// wprep: transpose + hi/lo split the 4 weight matrices into g_wh/g_wl [n][k].
// grid (16,16,4), 256 threads; 32x33 smem tile, coalesced both directions.
// =================================================================================
__global__ __launch_bounds__(256) void wprep(const float* __restrict__ W0,
                                             const float* __restrict__ W1,
                                             const float* __restrict__ W2,
                                             const float* __restrict__ W3)
{
    __shared__ float ts[32][33];
    const int z = blockIdx.z;
    const float* W = (z == 0) ? W0 : (z == 1) ? W1 : (z == 2) ? W2 : W3;
    const int bi = blockIdx.x, bj = blockIdx.y;     // k-tile, n-tile
    const int r = threadIdx.x & 31, c8 = threadIdx.x >> 5;

    #pragma unroll
    for (int cc = c8; cc < 32; cc += 8)             // ts[k_local][n_local]
        ts[cc][r] = W[(size_t)(bi*32 + cc)*DD + bj*32 + r];
    __syncthreads();

    #pragma unroll
    for (int nl = c8; nl < 32; nl += 8) {
        float v = ts[r][nl];                        // k_local = r (consecutive)
        __nv_bfloat16 hb, lb; bsplit(v, hb, lb);
        size_t o = (size_t)(bj*32 + nl)*DD + bi*32 + r;
        g_wh[z][o] = hb;
        g_wl[z][o] = lb;
    }
}

// =================================================================================
// mma projection GEMM: out[4096,512] = X @ W + bias, W pre-split/transposed.
// CTA 128x128, 8 warps x (32x64), K in 32-chunks, split-3 bf16 mma.
// mode 0: head-split scatter; mode 1: flat.
// =================================================================================
__device__ __forceinline__ void gemm_mma_body(const float* __restrict__ X,
                                              const __nv_bfloat16* __restrict__ WH,
                                              const __nv_bfloat16* __restrict__ WL,
                                              const float* __restrict__ bias,
                                              float* __restrict__ out, int mode)
{
    __shared__ __nv_bfloat16 Xh[128*40], Xl[128*40], Wh[128*40], Wl[128*40];
    const int t = threadIdx.x, lane = t & 31, wp = t >> 5;
    const int mi = wp & 3, nh = wp >> 2;
    const int m0 = blockIdx.x * 128, n0 = blockIdx.y * 128;

    float c[2][8][4];
    #pragma unroll
    for (int tm = 0; tm < 2; tm++)
        #pragma unroll
        for (int j = 0; j < 8; j++)
            #pragma unroll
            for (int e = 0; e < 4; e++) c[tm][j][e] = 0.f;

    for (int kb = 0; kb < DD; kb += 32) {
        __syncthreads();
        // X tile 128x32, split inline
        #pragma unroll
        for (int i = 0; i < 4; i++) {
            int idx = t + i*256;
            int m = idx >> 3, k4 = (idx & 7) * 4;
            float4 v = *(const float4*)(X + (size_t)(m0 + m)*DD + kb + k4);
            uint2 hi, lo; split4(v, hi, lo);
            *(uint2*)((char*)Xh + m*80 + k4*2) = hi;
            *(uint2*)((char*)Xl + m*80 + k4*2) = lo;
        }
        // W tiles 128x32 (pre-split [n][k])
        #pragma unroll
        for (int i = 0; i < 4; i++) {
            int idx = t + i*256;
            int n = idx >> 3, k4 = (idx & 7) * 4;
            *(uint2*)((char*)Wh + n*80 + k4*2) =
                *(const uint2*)(WH + (size_t)(n0 + n)*DD + kb + k4);
            *(uint2*)((char*)Wl + n*80 + k4*2) =
                *(const uint2*)(WL + (size_t)(n0 + n)*DD + kb + k4);
        }
        __syncthreads();

        #pragma unroll
        for (int kh = 0; kh < 2; kh++) {
            uint32_t Ah0[4], Ah1[4], Al0[4], Al1[4], Bh[2], Bl[2];
            LDSM_X4P(Ah0, Xh, mi*32,      kh*16);
            LDSM_X4P(Ah1, Xh, mi*32 + 16, kh*16);
            LDSM_X4P(Al0, Xl, mi*32,      kh*16);
            LDSM_X4P(Al1, Xl, mi*32 + 16, kh*16);
            #pragma unroll
            for (int j = 0; j < 8; j++) {
                int nb = (nh*8 + j)*8;
                LDSM_X2P(Bh, Wh, nb, kh*16);
                LDSM_X2P(Bl, Wl, nb, kh*16);
                MMA_BF16(c[0][j], Ah0, Bh);
                MMA_BF16(c[0][j], Ah0, Bl);
                MMA_BF16(c[0][j], Al0, Bh);
                MMA_BF16(c[1][j], Ah1, Bh);
                MMA_BF16(c[1][j], Ah1, Bl);
                MMA_BF16(c[1][j], Al1, Bh);
            }
        }
    }

    // epilogue
    const int rr = lane >> 2, cc = 2*(lane & 3);
    #pragma unroll
    for (int tm = 0; tm < 2; tm++) {
        int row = m0 + mi*32 + tm*16 + rr;
        int b_ = row >> 11, s2 = row & (SS - 1);
        #pragma unroll
        for (int j = 0; j < 8; j++) {
            int col = n0 + nh*64 + j*8 + cc;
            float bx = bias[col], by = bias[col + 1];
            float2 v01 = make_float2(c[tm][j][0] + bx, c[tm][j][1] + by);
            float2 v23 = make_float2(c[tm][j][2] + bx, c[tm][j][3] + by);
            if (mode == 0) {
                int hh = col >> 6, d = col & 63;
                size_t base = ((size_t)(b_*HH + hh)*SS + s2) << 6;
                *(float2*)(out + base + d) = v01;
                *(float2*)(out + base + ((size_t)8 << 6) + d) = v23;
            } else {
                *(float2*)(out + (size_t)row*DD + col) = v01;
                *(float2*)(out + (size_t)(row + 8)*DD + col) = v23;
            }
        }
    }
}

__global__ __launch_bounds__(256, 2) void gemm_qkv_mma(
    const float* __restrict__ q_in, const float* __restrict__ k_in,
    const float* __restrict__ v_in,
    const float* __restrict__ bq, const float* __restrict__ bk,
    const float* __restrict__ bv,
    float* __restrict__ gq, float* __restrict__ gk, float* __restrict__ gv)
{
    const float *X, *bias; float* out; int z = blockIdx.z;
    if (z == 0)      { X = q_in; bias = bq; out = gq; }
    else if (z == 1) { X = k_in; bias = bk; out = gk; }
    else             { X = v_in; bias = bv; out = gv; }
    gemm_mma_body(X, g_wh[z], g_wl[z], bias, out, 0);
}

__global__ __launch_bounds__(256, 2) void gemm_out_mma(
    const float* __restrict__ X, const float* __restrict__ bias,
    float* __restrict__ out)
{
    gemm_mma_body(X, g_wh[3], g_wl[3], bias, out, 1);
}

// =================================================================================
// attn smem byte offsets
// =================================================================================
#define PHV 72
#define B_QH 0
#define B_QL 9216
#define B_BH 18432
#define B_BL 36864
#define B_DK 55296      // float [64][68]
#define B_DE 72704      // float [64][132] ring (128 slots)
#define B_RM 106496
#define B_RS 106752
#define SM3_BYTES 107008
#define B_VH 18432
#define B_VL 27648
#define B_P2H 36864
#define B_P2L 46080

// =================================================================================
// Tensor-core fused attention — VERBATIM the R13-measured kernel (805.3 us):
// raw logits in phase 1, per-element expf normalize in phase 2.
// =================================================================================
__global__ __launch_bounds__(256, 2) void attn3(const float* __restrict__ E,
                                                float* __restrict__ attn)
{
    extern __shared__ char smc[];
    float* DK = (float*)(smc + B_DK);
    float* DE = (float*)(smc + B_DE);
    float* rm = (float*)(smc + B_RM);
    float* rs = (float*)(smc + B_RS);

    const int t    = threadIdx.x;
    const int lane = t & 31, wp = t >> 5;
    const int mi = wp & 3, nh = wp >> 2;
    const int qt = 31 - (int)blockIdx.x;
    const int q0 = qt * 64;
    const int h  = blockIdx.y, b = blockIdx.z;
    const int bh = b*HH + h;
    const float* qb = g_q + (size_t)bh*SS*DEP;
    const float* kb = g_k + (size_t)bh*SS*DEP;
    const float* vb = g_v + (size_t)bh*SS*DEP;
    float* arow_base = attn + ((size_t)bh*SS + q0) * SS;
    const int ql = t >> 2, ks4 = t & 3;
    const int nch = qt + 1;

    #pragma unroll
    for (int it = 0; it < 4; it++) {
        int idx = t + it*256;
        int r = idx >> 4, d4 = (idx & 15) << 2;
        float4 v = *(const float4*)(qb + (size_t)(q0 + r)*DEP + d4);
        uint2 hi, lo; split4(v, hi, lo);
        *(uint2*)(smc + B_QH + r*144 + d4*2) = hi;
        *(uint2*)(smc + B_QL + r*144 + d4*2) = lo;
    }
    {
        const int er0 = SS - 64 - q0;
        #pragma unroll
        for (int it = 0; it < 4; it++) {
            int idx = t + it*256;
            int r = idx >> 4, d4 = (idx & 15) << 2;
            float4 v = *(const float4*)(E + (size_t)(er0 + r)*DEP + d4);
            uint2 hi, lo; split4(v, hi, lo);
            *(uint2*)(smc + B_BH + r*144 + d4*2) = hi;
            *(uint2*)(smc + B_BL + r*144 + d4*2) = lo;
        }
    }
    if (t < 64) { rm[t] = -1e30f; rs[t] = 0.f; }
    __syncthreads();

    {
        float c[4][4];
        #pragma unroll
        for (int j = 0; j < 4; j++)
            #pragma unroll
            for (int e = 0; e < 4; e++) c[j][e] = 0.f;
        uint32_t Ah[4], Al[4], Bh[2], Bl[2];
        #pragma unroll
        for (int ks = 0; ks < 4; ks++) {
            LDSM_X4(Ah, smc + B_QH, mi*16, ks*16);
            LDSM_X4(Al, smc + B_QL, mi*16, ks*16);
            #pragma unroll
            for (int j = 0; j < 4; j++) {
                int n0 = (nh*4 + j)*8;
                LDSM_X2(Bh, smc + B_BH, n0, ks*16);
                LDSM_X2(Bl, smc + B_BL, n0, ks*16);
                MMA_BF16(c[j], Ah, Bh);
                MMA_BF16(c[j], Ah, Bl);
                MMA_BF16(c[j], Al, Bh);
            }
        }
        int r = mi*16 + (lane >> 2), cc = 2*(lane & 3);
        #pragma unroll
        for (int j = 0; j < 4; j++) {
            int col = (nh*4 + j)*8 + cc;
            *(float2*)(DE + r*132 + col)       = make_float2(c[j][0], c[j][1]);
            *(float2*)(DE + (r + 8)*132 + col) = make_float2(c[j][2], c[j][3]);
        }
    }
    __syncthreads();

    for (int kt = 0; kt < nch; kt++) {
        const int k0 = kt*64;
        #pragma unroll
        for (int it = 0; it < 4; it++) {
            int idx = t + it*256;
            int r = idx >> 4, d4 = (idx & 15) << 2;
            float4 v = *(const float4*)(kb + (size_t)(k0 + r)*DEP + d4);
            uint2 hi, lo; split4(v, hi, lo);
            *(uint2*)(smc + B_BH + r*144 + d4*2) = hi;
            *(uint2*)(smc + B_BL + r*144 + d4*2) = lo;
        }
        {
            const int ern = SS - q0 + 64*kt;
            #pragma unroll
            for (int it = 0; it < 4; it++) {
                int idx = t + it*256;
                int r = idx >> 4, d4 = (idx & 15) << 2;
                int er = ern + r;
                float4 v = (er < SS) ? *(const float4*)(E + (size_t)er*DEP + d4)
                                     : make_float4(0.f, 0.f, 0.f, 0.f);
                uint2 hi, lo; split4(v, hi, lo);
                *(uint2*)(smc + B_BH + (64 + r)*144 + d4*2) = hi;
                *(uint2*)(smc + B_BL + (64 + r)*144 + d4*2) = lo;
            }
        }
        __syncthreads();

        float c[8][4];
        #pragma unroll
        for (int j = 0; j < 8; j++)
            #pragma unroll
            for (int e = 0; e < 4; e++) c[j][e] = 0.f;
        {
            uint32_t Ah[4], Al[4], Bh[2], Bl[2];
            #pragma unroll
            for (int ks = 0; ks < 4; ks++) {
                LDSM_X4(Ah, smc + B_QH, mi*16, ks*16);
                LDSM_X4(Al, smc + B_QL, mi*16, ks*16);
                #pragma unroll
                for (int j = 0; j < 8; j++) {
                    int n0 = (nh*8 + j)*8;
                    LDSM_X2(Bh, smc + B_BH, n0, ks*16);
                    LDSM_X2(Bl, smc + B_BL, n0, ks*16);
                    MMA_BF16(c[j], Ah, Bh);
                    MMA_BF16(c[j], Ah, Bl);
                    MMA_BF16(c[j], Al, Bh);
                }
            }
        }
        {
            int r = mi*16 + (lane >> 2), cc = 2*(lane & 3);
            if (nh == 0) {
                #pragma unroll
                for (int j = 0; j < 8; j++) {
                    int col = j*8 + cc;
                    *(float2*)(DK + r*68 + col)       = make_float2(c[j][0], c[j][1]);
                    *(float2*)(DK + (r + 8)*68 + col) = make_float2(c[j][2], c[j][3]);
                }
            } else {
                int sb = (64*(kt + 1)) & 127;
                #pragma unroll
                for (int j = 0; j < 8; j++) {
                    int slot = sb + j*8 + cc;
                    *(float2*)(DE + r*132 + slot)       = make_float2(c[j][0], c[j][1]);
                    *(float2*)(DE + (r + 8)*132 + slot) = make_float2(c[j][2], c[j][3]);
                }
            }
        }
        __syncthreads();

        const float* dkr = DK + ql*68;
        const float* der = DE + ql*132;
        const int slotbase = 64*kt + 63 - ql;
        float l[16];
        float lmax = -1e30f;
        #pragma unroll
        for (int j = 0; j < 16; j++) {
            int kl = ks4 + 4*j;
            float v = dkr[kl] + der[(slotbase + kl) & 127];
            v = (k0 + kl <= q0 + ql) ? v*0.125f : -1e30f;
            l[j] = v;
            lmax = fmaxf(lmax, v);
        }
        float lsum = 0.f;
        #pragma unroll
        for (int j = 0; j < 16; j++) lsum += __expf(l[j] - lmax);

        float* ar = arow_base + (size_t)ql*SS + k0;
        #pragma unroll
        for (int j = 0; j < 16; j++) ar[ks4 + 4*j] = l[j];

        #pragma unroll
        for (int off = 1; off < 4; off <<= 1) {
            float om = __shfl_xor_sync(0xffffffffu, lmax, off);
            float os = __shfl_xor_sync(0xffffffffu, lsum, off);
            float nm = fmaxf(lmax, om);
            lsum = lsum*__expf(lmax - nm) + os*__expf(om - nm);
            lmax = nm;
        }
        if (ks4 == 0) {
            float mo = rm[ql];
            float nm = fmaxf(mo, lmax);
            rs[ql] = rs[ql]*__expf(mo - nm) + lsum*__expf(lmax - nm);
            rm[ql] = nm;
        }
        __syncthreads();
    }

    const float rmax = rm[ql];
    const float rinv = 1.f / rs[ql];

    __nv_bfloat16* Vh  = (__nv_bfloat16*)(smc + B_VH);
    __nv_bfloat16* Vl  = (__nv_bfloat16*)(smc + B_VL);
    __nv_bfloat16* P2h = (__nv_bfloat16*)(smc + B_P2H);
    __nv_bfloat16* P2l = (__nv_bfloat16*)(smc + B_P2L);
    float o[4][4];
    #pragma unroll
    for (int j = 0; j < 4; j++)
        #pragma unroll
        for (int e = 0; e < 4; e++) o[j][e] = 0.f;

    for (int kt = 0; kt < nch; kt++) {
        const int k0 = kt*64;
        __syncthreads();
        #pragma unroll
        for (int it = 0; it < 4; it++) {
            int idx = t + it*256;
            int k = idx >> 4, d4 = (idx & 15) << 2;
            float4 v = *(const float4*)(vb + (size_t)(k0 + k)*DEP + d4);
            float vv[4] = {v.x, v.y, v.z, v.w};
            #pragma unroll
            for (int e = 0; e < 4; e++) {
                __nv_bfloat16 hb, lb; bsplit(vv[e], hb, lb);
                Vh[(d4 + e)*PHV + k] = hb;
                Vl[(d4 + e)*PHV + k] = lb;
            }
        }
        float* ar = arow_base + (size_t)ql*SS + k0;
        #pragma unroll
        for (int j = 0; j < 16; j++) {
            int kl = ks4 + 4*j;
            float wgt = __expf(ar[kl] - rmax) * rinv;
            ar[kl] = wgt;
            __nv_bfloat16 hb, lb; bsplit(wgt, hb, lb);
            P2h[ql*PHV + kl] = hb;
            P2l[ql*PHV + kl] = lb;
        }
        __syncthreads();
        {
            uint32_t Ah[4], Al[4], Bh[2], Bl[2];
            #pragma unroll
            for (int ks = 0; ks < 4; ks++) {
                LDSM_X4(Ah, smc + B_P2H, mi*16, ks*16);
                LDSM_X4(Al, smc + B_P2L, mi*16, ks*16);
                #pragma unroll
                for (int j = 0; j < 4; j++) {
                    int n0 = (nh*4 + j)*8;
                    LDSM_X2(Bh, smc + B_VH, n0, ks*16);
                    LDSM_X2(Bl, smc + B_VL, n0, ks*16);
                    MMA_BF16(o[j], Ah, Bh);
                    MMA_BF16(o[j], Ah, Bl);
                    MMA_BF16(o[j], Al, Bh);
                }
            }
        }
    }

    const int kstart = nch*64;
    if (kstart < SS) {
        const int len4 = (SS - kstart) >> 2;
        const int tot = 64 * len4;
        for (int idx = t; idx < tot; idx += 256) {
            int row = idx / len4, ccc = idx - row*len4;
            ((float4*)(arow_base + (size_t)row*SS + kstart))[ccc] =
                make_float4(0.f, 0.f, 0.f, 0.f);
        }
    }

    {
        int r = mi*16 + (lane >> 2), cc = 2*(lane & 3);
        #pragma unroll
        for (int j = 0; j < 4; j++) {
            int d = (nh*4 + j)*8 + cc;
            *(float2*)(g_c + ((size_t)b*SS + q0 + r)*DD + h*64 + d) =
                make_float2(o[j][0], o[j][1]);
            *(float2*)(g_c + ((size_t)b*SS + q0 + r + 8)*DD + h*64 + d) =
                make_float2(o[j][2], o[j][3]);
        }
    }
}

// =================================================================================
// launch
// inputs: 0 v_in, 1 k_in, 2 q_in, 3 mask(unused), 4 Wq, 5 bq, 6 Wk, 7 bk,
//         8 Wv, 9 bv, 10 Wo, 11 bo, 12 E
// output: [output (B*S*D floats)] ++ [attention_weights (B*H*S*S floats)]
// =================================================================================
extern "C" void kernel_launch(void* const* d_in, const int* in_sizes, int n_in,
                              void* d_out, int out_size)
{
    (void)in_sizes; (void)n_in; (void)out_size;
    const float* v_in = (const float*)d_in[0];
    const float* k_in = (const float*)d_in[1];
    const float* q_in = (const float*)d_in[2];
    const float* Wq   = (const float*)d_in[4];
    const float* bq   = (const float*)d_in[5];
    const float* Wk   = (const float*)d_in[6];
    const float* bk   = (const float*)d_in[7];
    const float* Wv   = (const float*)d_in[8];
    const float* bv   = (const float*)d_in[9];
    const float* Wo   = (const float*)d_in[10];
    const float* bo   = (const float*)d_in[11];
    const float* E    = (const float*)d_in[12];

    float* out  = (float*)d_out;
    float* attn = out + (size_t)BSD;

    float *gq, *gk, *gv, *gc;
    cudaGetSymbolAddress((void**)&gq, g_q);
    cudaGetSymbolAddress((void**)&gk, g_k);
    cudaGetSymbolAddress((void**)&gv, g_v);
    cudaGetSymbolAddress((void**)&gc, g_c);

    cudaFuncSetAttribute(attn3,
                         cudaFuncAttributeMaxDynamicSharedMemorySize, SM3_BYTES);

    wprep<<<dim3(16, 16, 4), 256>>>(Wq, Wk, Wv, Wo);
    gemm_qkv_mma<<<dim3(32, 4, 3), 256>>>(q_in, k_in, v_in,
                                          bq, bk, bv, gq, gk, gv);
    attn3<<<dim3(32, HH, BB), 256, SM3_BYTES>>>(E, attn);
    gemm_out_mma<<<dim3(32, 4), 256>>>(gc, bo, out);
}